// round 16
// baseline (speedup 1.0000x reference)
#include <cuda_runtime.h>
#include <math.h>

#define NN     50000
#define RR     4
#define DD     5
#define BB     8
#define TT     10
#define E_RECN 1500000
#define E_INN  200000
#define N_INN  17400
#define RNN    (RR * NN)   // 200000
#define ZLEN   (DD * NN)   // 250000
#define IN_QUADS (E_INN / 4)   // 50000

#define U_BLKS   391           // ceil(2*50000/256) -- one thread per (n, batch-half)
#define SE_BLKS  1280
#define F_GRID   (U_BLKS + SE_BLKS)

#define D0_SLOT  32            // fixed slots per source neuron for d=0 edges
#define SEG_CAP  420000        // capacity per delay list d=1..4 (expected ~300K)

// ------------------------- device scratch (no allocs) -------------------------
__device__ float4         g_totA[BB * NN];
__device__ float4         g_totB[BB * NN];
__device__ float          g_v[BB * NN];
__device__ float          g_r[BB * NN];
__device__ float          g_a1[BB * NN];
__device__ float          g_a2[BB * NN];
__device__ float4         g_psc_rise[BB * NN];
__device__ float4         g_psc[BB * NN];
__device__ unsigned char  g_zmask[ZLEN];
__device__ unsigned char  g_xmask[TT * N_INN];
__device__ float2         g_ascd[NN];

// delay-partitioned edge lists, fixed segments of SEG_CAP for d = 1..4
__device__ unsigned short g_e_n16[4 * SEG_CAP];   // source neuron, 16-bit (NN < 65536)
__device__ int            g_e_tgt [4 * SEG_CAP];
__device__ float          g_e_w   [4 * SEG_CAP];
__device__ int            g_dfill[4];   // append cursors (= counts after partition)
__device__ int            g_qoff[5];    // quad-offset prefix over delay lists

// d=0 edges: fixed-slot buckets per source neuron (no hist/scan needed)
__device__ int            g_fill0[NN];            // cursor, init = n*D0_SLOT
__device__ int2           g_d0_edge[NN * D0_SLOT];

// per-source-step spike activity flags: g_any[5 + s] for step s (s in [-5, TT))
__device__ int            g_any[16];

// ------------------------------- init kernel ---------------------------------
__global__ void init_kernel(const float* __restrict__ x,
                            const float* __restrict__ bkg_w,
                            const float2* __restrict__ param_k,
                            const float* __restrict__ v0)
{
    int i      = blockIdx.x * blockDim.x + threadIdx.x;
    int stride = gridDim.x * blockDim.x;

    if (i < 16) g_any[i] = 0;
    if (i < 4)  g_dfill[i] = 0;

    const float4* bkg4 = reinterpret_cast<const float4*>(bkg_w);
    for (int j = i; j < BB * NN; j += stride) {
        float4 bk = bkg4[j % NN];
        g_totA[j] = bk;
        g_totB[j] = bk;
        g_v[j]  = v0[j];
        g_r[j]  = 0.0f;
        g_a1[j] = 0.0f;
        g_a2[j] = 0.0f;
        g_psc_rise[j] = make_float4(0.f, 0.f, 0.f, 0.f);
        g_psc[j]      = make_float4(0.f, 0.f, 0.f, 0.f);
    }
    for (int j = i; j < ZLEN; j += stride) g_zmask[j] = 0;
    for (int j = i; j < NN; j += stride) g_fill0[j] = j * D0_SLOT;
    for (int j = i; j < TT * N_INN; j += stride) {
        int t = j / N_INN;
        int s = j - t * N_INN;
        unsigned m = 0;
        #pragma unroll
        for (int b = 0; b < BB; b++) {
            if (x[(t * BB + b) * N_INN + s] > 0.5f) m |= (1u << b);
        }
        g_xmask[j] = (unsigned char)m;
    }
    for (int j = i; j < NN; j += stride) {
        float2 pk = param_k[j];
        float s0 = 1.0f / (1.0f + expf(-pk.x));
        float s1 = 1.0f / (1.0f + expf(-pk.y));
        g_ascd[j] = make_float2(expf(-s0), expf(-s1));
    }
}

// ---------------------- partition edges into fixed segments --------------------
__global__ __launch_bounds__(256)
void partition_kernel(const int* __restrict__ rec_src,
                      const int* __restrict__ rec_tgt,
                      const float* __restrict__ w_rec)
{
    __shared__ int scnt[4], sbase[4];
    if (threadIdx.x < 4) scnt[threadIdx.x] = 0;
    __syncthreads();

    int e = blockIdx.x * blockDim.x + threadIdx.x;
    int d = 0, n = 0, tgt = 0, ticket = -1;
    float w = 0.0f;
    if (e < E_RECN) {
        int src = rec_src[e];
        d = src / NN;
        n = src - d * NN;
        tgt = rec_tgt[e];
        w   = w_rec[e];
        if (d == 0) {
            int pos = atomicAdd(&g_fill0[n], 1);
            g_d0_edge[pos] = make_int2(tgt, __float_as_int(w));
        } else {
            ticket = atomicAdd(&scnt[d - 1], 1);
        }
    }
    __syncthreads();
    if (threadIdx.x < 4 && scnt[threadIdx.x] > 0)
        sbase[threadIdx.x] = atomicAdd(&g_dfill[threadIdx.x], scnt[threadIdx.x]);
    __syncthreads();
    if (ticket >= 0) {
        int pos = (d - 1) * SEG_CAP + sbase[d - 1] + ticket;
        g_e_n16[pos] = (unsigned short)n;
        g_e_tgt[pos] = tgt;
        g_e_w[pos]   = w;
    }
}

// -------- step-0 input scatter + (block 0) segment pad & quad offsets ----------
__global__ __launch_bounds__(256)
void s0_kernel(const int* __restrict__ in_src,
               const int* __restrict__ in_tgt,
               const float* __restrict__ w_in)
{
    if (blockIdx.x == 0) {
        int tid = threadIdx.x;
        if (tid < 4) {
            int cnt = g_dfill[tid];
            int end = ((cnt + 3) >> 2) << 2;
            int base = tid * SEG_CAP;
            for (int p = cnt; p < end; p++) {
                g_e_n16[base + p] = 0;
                g_e_tgt[base + p] = 0;
                g_e_w[base + p]   = 0.0f;
            }
        }
        if (tid == 0) {
            int acc = 0;
            g_qoff[0] = 0;
            #pragma unroll
            for (int d = 0; d < 4; d++) {
                acc += (g_dfill[d] + 3) >> 2;
                g_qoff[d + 1] = acc;
            }
        }
    }

    int q = blockIdx.x * blockDim.x + threadIdx.x;
    if (q >= IN_QUADS) return;
    float* tot = reinterpret_cast<float*>(g_totA);
    const int e0 = q * 4;
    int4 si = *reinterpret_cast<const int4*>(&in_src[e0]);
    const unsigned char* xm = &g_xmask[0];
    unsigned m0 = xm[si.x], m1 = xm[si.y], m2 = xm[si.z], m3 = xm[si.w];
    if ((m0 | m1 | m2 | m3) == 0u) return;
    int4   tg = *reinterpret_cast<const int4*>  (&in_tgt[e0]);
    float4 ww = *reinterpret_cast<const float4*>(&w_in[e0]);
    unsigned ms[4]  = {m0, m1, m2, m3};
    int      tgs[4] = {tg.x, tg.y, tg.z, tg.w};
    float    wws[4] = {ww.x, ww.y, ww.z, ww.w};
    #pragma unroll
    for (int k = 0; k < 4; k++) {
        unsigned m = ms[k];
        if (!m) continue;
        #pragma unroll
        for (int b = 0; b < BB; b++) {
            if (m & (1u << b)) atomicAdd(&tot[b * RNN + tgs[k]], wws[k]);
        }
    }
}

// ------------------------------ fused step kernel -------------------------------
// Update role: one thread per (neuron, batch-half); pair lanes (2i, 2i+1) share
//   neuron i, handle batches 0-3 / 4-7, recombine spike mask via shfl_xor.
// Scatter role: unchanged quad-per-thread over delay segments + input edges.
__global__ __launch_bounds__(256)
void fused_kernel(const float*  __restrict__ decay,
                  const float*  __restrict__ current_factor,
                  const float*  __restrict__ v_th,
                  const float*  __restrict__ e_l,
                  const float*  __restrict__ v_reset,
                  const float*  __restrict__ t_ref,
                  const float2* __restrict__ asc_amps,
                  const float*  __restrict__ param_g,
                  const float4* __restrict__ syn_decay,
                  const float4* __restrict__ psc_initial,
                  const float4* __restrict__ bkg4,
                  const int*    __restrict__ in_src,
                  const int*    __restrict__ in_tgt,
                  const float*  __restrict__ w_in,
                  float*        __restrict__ out,
                  int t, int h_read, int h_write)
{
    float4* totcur = (t & 1) ? g_totB : g_totA;
    float4* totnxt = (t & 1) ? g_totA : g_totB;

    if (blockIdx.x < U_BLKS) {
        // ------------------------- update role -------------------------------
        int gid = blockIdx.x * blockDim.x + threadIdx.x;
        if (gid >= 2 * NN) return;          // 2*NN divisible by 32 -> warp-aligned exit
        int n = gid >> 1;
        int h = gid & 1;                    // batch half: batches 4h .. 4h+3

        const float  dec  = decay[n];
        const float  cf   = current_factor[n];
        const float  vth  = v_th[n];
        const float  el   = e_l[n];
        const float  vre  = v_reset[n];
        const float  tref = t_ref[n];
        const float2 amps = asc_amps[n];
        const float2 ad   = g_ascd[n];
        const float  g    = param_g[n];
        const float4 sd   = syn_decay[n];
        const float4 pi   = psc_initial[n];
        const float4 bk   = bkg4[n];

        const float gel    = g * el;
        const float invden = 1.0f / (vth - el);
        const float rstamp = vre - vth;

        unsigned pm = ((unsigned)g_zmask[h_read * NN + n] >> (4 * h)) & 0xFu;
        unsigned hm = 0;

        #pragma unroll
        for (int bb = 0; bb < 4; bb++) {
            int b  = 4 * h + bb;
            int bn = b * NN + n;
            float4 total = totcur[bn];
            float4 pr = g_psc_rise[bn];
            float4 pc = g_psc[bn];
            float  v  = g_v[bn];
            float  r  = g_r[bn];
            float  a1 = g_a1[bn];
            float  a2 = g_a2[bn];
            float  pz = (pm >> bb) & 1u ? 1.0f : 0.0f;

            float input_cur = pc.x + pc.y + pc.z + pc.w;
            float c1   = input_cur + a1 + a2 + gel;
            float newv = dec * v + cf * c1 + pz * rstamp;
            float newr = fmaxf(r + pz * tref - 1.0f, 0.0f);
            float na1  = ad.x * a1 + pz * amps.x;
            float na2  = ad.y * a2 + pz * amps.y;

            float4 npc, npr;
            npc.x = pc.x * sd.x + sd.x * pr.x;
            npc.y = pc.y * sd.y + sd.y * pr.y;
            npc.z = pc.z * sd.z + sd.z * pr.z;
            npc.w = pc.w * sd.w + sd.w * pr.w;
            npr.x = sd.x * pr.x + pi.x * total.x;
            npr.y = sd.y * pr.y + pi.y * total.y;
            npr.z = sd.z * pr.z + pi.z * total.z;
            npr.w = sd.w * pr.w + pi.w * total.w;

            float vsc = (newv - vth) * invden;
            float z = (vsc > 0.0f) ? 1.0f : 0.0f;
            if (newr > 0.0f) z = 0.0f;
            hm |= (z != 0.0f ? 1u : 0u) << bb;

            g_v[bn]  = newv;
            g_r[bn]  = newr;
            g_a1[bn] = na1;
            g_a2[bn] = na2;
            g_psc_rise[bn] = npr;
            g_psc[bn]      = npc;
            totcur[bn] = bk;                 // re-init for step t+2

            __stcs(&out[(t * BB + b) * NN + n], z);
        }

        // recombine 8-bit spike mask across the lane pair
        unsigned other = __shfl_xor_sync(0xffffffffu, hm, 1);
        unsigned nm = h ? ((hm << 4) | other) : (hm | (other << 4));

        if (h == 0) {
            g_zmask[h_write * NN + n] = (unsigned char)nm;
            if (nm) {
                g_any[5 + t] = 1;            // benign race (all write 1)
                if (t + 1 < TT) {
                    float* totn = reinterpret_cast<float*>(totnxt);
                    int base = n * D0_SLOT;
                    int r1 = g_fill0[n];
                    for (int e = base; e < r1; e++) {
                        int2 tw = g_d0_edge[e];
                        float w = __int_as_float(tw.y);
                        #pragma unroll
                        for (int b = 0; b < BB; b++) {
                            if (nm & (1u << b)) atomicAdd(&totn[b * RNN + tw.x], w);
                        }
                    }
                }
            }
        }
    } else {
        // --------------------- scatter role (step t+1) -----------------------
        if (t + 1 >= TT) return;
        const int tau = t + 1;
        float* totn = reinterpret_cast<float*>(totnxt);

        const int q1 = g_qoff[1];
        const int q2 = g_qoff[2];
        const int q3 = g_qoff[3];
        const int q4 = g_qoff[4];
        const int totq = q4 + IN_QUADS;

        int idx    = (blockIdx.x - U_BLKS) * blockDim.x + threadIdx.x;
        int stride = (gridDim.x - U_BLKS) * blockDim.x;

        for (int q = idx; q < totq; q += stride) {
            if (q < q4) {
                int d = 1 + (q >= q1) + (q >= q2) + (q >= q3);
                if (g_any[5 + t - d] == 0) continue;   // source step had no spikes
                int qbase = (d == 1) ? 0 : (d == 2) ? q1 : (d == 3) ? q2 : q3;
                const int e0 = (d - 1) * SEG_CAP + ((q - qbase) << 2);

                int slot = h_write + d; if (slot >= DD) slot -= DD;
                const unsigned char* zm = &g_zmask[slot * NN];

                ushort4 nn = *reinterpret_cast<const ushort4*>(&g_e_n16[e0]);
                unsigned m0 = zm[nn.x], m1 = zm[nn.y], m2 = zm[nn.z], m3 = zm[nn.w];
                if ((m0 | m1 | m2 | m3) == 0u) continue;

                int4   tg = *reinterpret_cast<const int4*>  (&g_e_tgt[e0]);
                float4 ww = *reinterpret_cast<const float4*>(&g_e_w[e0]);
                unsigned ms[4]  = {m0, m1, m2, m3};
                int      tgs[4] = {tg.x, tg.y, tg.z, tg.w};
                float    wws[4] = {ww.x, ww.y, ww.z, ww.w};
                #pragma unroll
                for (int k = 0; k < 4; k++) {
                    unsigned m = ms[k];
                    if (!m) continue;
                    #pragma unroll
                    for (int b = 0; b < BB; b++) {
                        if (m & (1u << b)) atomicAdd(&totn[b * RNN + tgs[k]], wws[k]);
                    }
                }
            } else {
                const int e0 = (q - q4) * 4;
                int4 si = *reinterpret_cast<const int4*>(&in_src[e0]);
                const unsigned char* xm = &g_xmask[tau * N_INN];
                unsigned m0 = xm[si.x], m1 = xm[si.y], m2 = xm[si.z], m3 = xm[si.w];
                if ((m0 | m1 | m2 | m3) == 0u) continue;

                int4   tg = *reinterpret_cast<const int4*>  (&in_tgt[e0]);
                float4 ww = *reinterpret_cast<const float4*>(&w_in[e0]);
                unsigned ms[4]  = {m0, m1, m2, m3};
                int      tgs[4] = {tg.x, tg.y, tg.z, tg.w};
                float    wws[4] = {ww.x, ww.y, ww.z, ww.w};
                #pragma unroll
                for (int k = 0; k < 4; k++) {
                    unsigned m = ms[k];
                    if (!m) continue;
                    #pragma unroll
                    for (int b = 0; b < BB; b++) {
                        if (m & (1u << b)) atomicAdd(&totn[b * RNN + tgs[k]], wws[k]);
                    }
                }
            }
        }
    }
}

// --------------------------------- launcher ----------------------------------
extern "C" void kernel_launch(void* const* d_in, const int* in_sizes, int n_in,
                              void* d_out, int out_size)
{
    const float* x        = (const float*)d_in[0];
    const float* w_rec    = (const float*)d_in[1];
    const int*   rec_src  = (const int*)  d_in[2];
    const int*   rec_tgt  = (const int*)  d_in[3];
    const float* w_in     = (const float*)d_in[4];
    const int*   in_src   = (const int*)  d_in[5];
    const int*   in_tgt   = (const int*)  d_in[6];
    const float* bkg_w    = (const float*)d_in[7];
    const float* decay    = (const float*)d_in[8];
    const float* cf       = (const float*)d_in[9];
    const float* v_th     = (const float*)d_in[10];
    const float* e_l      = (const float*)d_in[11];
    const float* v_reset  = (const float*)d_in[12];
    const float* t_ref    = (const float*)d_in[13];
    const float2* asc_amps = (const float2*)d_in[14];
    const float2* param_k  = (const float2*)d_in[15];
    const float* param_g   = (const float*)d_in[16];
    const float4* syn_decay   = (const float4*)d_in[17];
    const float4* psc_initial = (const float4*)d_in[18];
    const float* v0        = (const float*)d_in[19];
    float* out = (float*)d_out;

    init_kernel<<<1024, 256>>>(x, bkg_w, param_k, v0);
    partition_kernel<<<(E_RECN + 255) / 256, 256>>>(rec_src, rec_tgt, w_rec);
    s0_kernel<<<(IN_QUADS + 255) / 256, 256>>>(in_src, in_tgt, w_in);

    int h = 0;
    for (int t = 0; t < TT; t++) {
        int h_read  = h;
        int h_write = (h + DD - 1) % DD;
        fused_kernel<<<F_GRID, 256>>>(decay, cf, v_th, e_l, v_reset, t_ref,
                                      asc_amps, param_g, syn_decay, psc_initial,
                                      (const float4*)bkg_w,
                                      in_src, in_tgt, w_in,
                                      out, t, h_read, h_write);
        h = h_write;
    }
}

// round 17
// speedup vs baseline: 1.1782x; 1.1782x over previous
#include <cuda_runtime.h>
#include <math.h>

#define NN     50000
#define RR     4
#define DD     5
#define BB     8
#define TT     10
#define E_RECN 1500000
#define E_INN  200000
#define N_INN  17400
#define RNN    (RR * NN)   // 200000
#define ZLEN   (DD * NN)   // 250000
#define IN_QUADS (E_INN / 4)   // 50000

#define U_BLKS   196           // ceil(50000/256)
#define SE_BLKS  248           // single-wave grid: 196+248 = 444 = 3 CTAs/SM * 148 SMs
#define F_GRID   (U_BLKS + SE_BLKS)

#define D0_SLOT  32            // fixed slots per source neuron for d=0 edges
#define SEG_CAP  420000        // capacity per delay list d=1..4 (expected ~300K)

// ------------------------- device scratch (no allocs) -------------------------
__device__ float4         g_totA[BB * NN];
__device__ float4         g_totB[BB * NN];
__device__ float          g_v[BB * NN];
__device__ float          g_r[BB * NN];
__device__ float          g_a1[BB * NN];
__device__ float          g_a2[BB * NN];
__device__ float4         g_psc_rise[BB * NN];
__device__ float4         g_psc[BB * NN];
__device__ unsigned char  g_zmask[ZLEN];
__device__ unsigned char  g_xmask[TT * N_INN];
__device__ float2         g_ascd[NN];

// delay-partitioned edge lists, fixed segments of SEG_CAP for d = 1..4
__device__ unsigned short g_e_n16[4 * SEG_CAP];   // source neuron, 16-bit (NN < 65536)
__device__ int            g_e_tgt [4 * SEG_CAP];
__device__ float          g_e_w   [4 * SEG_CAP];
__device__ int            g_dfill[4];   // append cursors (= counts after partition)
__device__ int            g_qoff[5];    // quad-offset prefix over delay lists

// d=0 edges: fixed-slot buckets per source neuron (no hist/scan needed)
__device__ int            g_fill0[NN];            // cursor, init = n*D0_SLOT
__device__ int2           g_d0_edge[NN * D0_SLOT];

// per-source-step spike activity flags: g_any[5 + s] for step s (s in [-5, TT))
__device__ int            g_any[16];

// ------------------------------- init kernel ---------------------------------
__global__ void init_kernel(const float* __restrict__ x,
                            const float* __restrict__ bkg_w,
                            const float2* __restrict__ param_k,
                            const float* __restrict__ v0)
{
    int i      = blockIdx.x * blockDim.x + threadIdx.x;
    int stride = gridDim.x * blockDim.x;

    if (i < 16) g_any[i] = 0;
    if (i < 4)  g_dfill[i] = 0;

    const float4* bkg4 = reinterpret_cast<const float4*>(bkg_w);
    for (int j = i; j < BB * NN; j += stride) {
        float4 bk = bkg4[j % NN];
        g_totA[j] = bk;
        g_totB[j] = bk;
        g_v[j]  = v0[j];
        g_r[j]  = 0.0f;
        g_a1[j] = 0.0f;
        g_a2[j] = 0.0f;
        g_psc_rise[j] = make_float4(0.f, 0.f, 0.f, 0.f);
        g_psc[j]      = make_float4(0.f, 0.f, 0.f, 0.f);
    }
    for (int j = i; j < ZLEN; j += stride) g_zmask[j] = 0;
    for (int j = i; j < NN; j += stride) g_fill0[j] = j * D0_SLOT;
    for (int j = i; j < TT * N_INN; j += stride) {
        int t = j / N_INN;
        int s = j - t * N_INN;
        unsigned m = 0;
        #pragma unroll
        for (int b = 0; b < BB; b++) {
            if (x[(t * BB + b) * N_INN + s] > 0.5f) m |= (1u << b);
        }
        g_xmask[j] = (unsigned char)m;
    }
    for (int j = i; j < NN; j += stride) {
        float2 pk = param_k[j];
        float s0 = 1.0f / (1.0f + expf(-pk.x));
        float s1 = 1.0f / (1.0f + expf(-pk.y));
        g_ascd[j] = make_float2(expf(-s0), expf(-s1));
    }
}

// ---------------------- partition edges into fixed segments --------------------
__global__ __launch_bounds__(256)
void partition_kernel(const int* __restrict__ rec_src,
                      const int* __restrict__ rec_tgt,
                      const float* __restrict__ w_rec)
{
    __shared__ int scnt[4], sbase[4];
    if (threadIdx.x < 4) scnt[threadIdx.x] = 0;
    __syncthreads();

    int e = blockIdx.x * blockDim.x + threadIdx.x;
    int d = 0, n = 0, tgt = 0, ticket = -1;
    float w = 0.0f;
    if (e < E_RECN) {
        int src = rec_src[e];
        d = src / NN;
        n = src - d * NN;
        tgt = rec_tgt[e];
        w   = w_rec[e];
        if (d == 0) {
            int pos = atomicAdd(&g_fill0[n], 1);
            g_d0_edge[pos] = make_int2(tgt, __float_as_int(w));
        } else {
            ticket = atomicAdd(&scnt[d - 1], 1);
        }
    }
    __syncthreads();
    if (threadIdx.x < 4 && scnt[threadIdx.x] > 0)
        sbase[threadIdx.x] = atomicAdd(&g_dfill[threadIdx.x], scnt[threadIdx.x]);
    __syncthreads();
    if (ticket >= 0) {
        int pos = (d - 1) * SEG_CAP + sbase[d - 1] + ticket;
        g_e_n16[pos] = (unsigned short)n;
        g_e_tgt[pos] = tgt;
        g_e_w[pos]   = w;
    }
}

// -------- step-0 input scatter + (block 0) segment pad & quad offsets ----------
__global__ __launch_bounds__(256)
void s0_kernel(const int* __restrict__ in_src,
               const int* __restrict__ in_tgt,
               const float* __restrict__ w_in)
{
    if (blockIdx.x == 0) {
        int tid = threadIdx.x;
        if (tid < 4) {
            int cnt = g_dfill[tid];
            int end = ((cnt + 3) >> 2) << 2;
            int base = tid * SEG_CAP;
            for (int p = cnt; p < end; p++) {
                g_e_n16[base + p] = 0;
                g_e_tgt[base + p] = 0;
                g_e_w[base + p]   = 0.0f;
            }
        }
        if (tid == 0) {
            int acc = 0;
            g_qoff[0] = 0;
            #pragma unroll
            for (int d = 0; d < 4; d++) {
                acc += (g_dfill[d] + 3) >> 2;
                g_qoff[d + 1] = acc;
            }
        }
    }

    int q = blockIdx.x * blockDim.x + threadIdx.x;
    if (q >= IN_QUADS) return;
    float* tot = reinterpret_cast<float*>(g_totA);
    const int e0 = q * 4;
    int4 si = *reinterpret_cast<const int4*>(&in_src[e0]);
    const unsigned char* xm = &g_xmask[0];
    unsigned m0 = xm[si.x], m1 = xm[si.y], m2 = xm[si.z], m3 = xm[si.w];
    if ((m0 | m1 | m2 | m3) == 0u) return;
    int4   tg = *reinterpret_cast<const int4*>  (&in_tgt[e0]);
    float4 ww = *reinterpret_cast<const float4*>(&w_in[e0]);
    unsigned ms[4]  = {m0, m1, m2, m3};
    int      tgs[4] = {tg.x, tg.y, tg.z, tg.w};
    float    wws[4] = {ww.x, ww.y, ww.z, ww.w};
    #pragma unroll
    for (int k = 0; k < 4; k++) {
        unsigned m = ms[k];
        if (!m) continue;
        #pragma unroll
        for (int b = 0; b < BB; b++) {
            if (m & (1u << b)) atomicAdd(&tot[b * RNN + tgs[k]], wws[k]);
        }
    }
}

// ------------------------------ fused step kernel -------------------------------
__global__ __launch_bounds__(256)
void fused_kernel(const float*  __restrict__ decay,
                  const float*  __restrict__ current_factor,
                  const float*  __restrict__ v_th,
                  const float*  __restrict__ e_l,
                  const float*  __restrict__ v_reset,
                  const float*  __restrict__ t_ref,
                  const float2* __restrict__ asc_amps,
                  const float*  __restrict__ param_g,
                  const float4* __restrict__ syn_decay,
                  const float4* __restrict__ psc_initial,
                  const float4* __restrict__ bkg4,
                  const int*    __restrict__ in_src,
                  const int*    __restrict__ in_tgt,
                  const float*  __restrict__ w_in,
                  float*        __restrict__ out,
                  int t, int h_read, int h_write)
{
    float4* totcur = (t & 1) ? g_totB : g_totA;
    float4* totnxt = (t & 1) ? g_totA : g_totB;

    if (blockIdx.x < U_BLKS) {
        // ------------------------- update role -------------------------------
        int n = blockIdx.x * blockDim.x + threadIdx.x;
        if (n >= NN) return;

        const float  dec  = decay[n];
        const float  cf   = current_factor[n];
        const float  vth  = v_th[n];
        const float  el   = e_l[n];
        const float  vre  = v_reset[n];
        const float  tref = t_ref[n];
        const float2 amps = asc_amps[n];
        const float2 ad   = g_ascd[n];
        const float  g    = param_g[n];
        const float4 sd   = syn_decay[n];
        const float4 pi   = psc_initial[n];
        const float4 bk   = bkg4[n];

        const float gel    = g * el;
        const float invden = 1.0f / (vth - el);
        const float rstamp = vre - vth;

        unsigned pm = g_zmask[h_read * NN + n];
        unsigned nm = 0;

        #pragma unroll
        for (int b = 0; b < BB; b++) {
            int bn = b * NN + n;
            float4 total = totcur[bn];
            float4 pr = g_psc_rise[bn];
            float4 pc = g_psc[bn];
            float  v  = g_v[bn];
            float  r  = g_r[bn];
            float  a1 = g_a1[bn];
            float  a2 = g_a2[bn];
            float  pz = (pm >> b) & 1u ? 1.0f : 0.0f;

            float input_cur = pc.x + pc.y + pc.z + pc.w;
            float c1   = input_cur + a1 + a2 + gel;
            float newv = dec * v + cf * c1 + pz * rstamp;
            float newr = fmaxf(r + pz * tref - 1.0f, 0.0f);
            float na1  = ad.x * a1 + pz * amps.x;
            float na2  = ad.y * a2 + pz * amps.y;

            float4 npc, npr;
            npc.x = pc.x * sd.x + sd.x * pr.x;
            npc.y = pc.y * sd.y + sd.y * pr.y;
            npc.z = pc.z * sd.z + sd.z * pr.z;
            npc.w = pc.w * sd.w + sd.w * pr.w;
            npr.x = sd.x * pr.x + pi.x * total.x;
            npr.y = sd.y * pr.y + pi.y * total.y;
            npr.z = sd.z * pr.z + pi.z * total.z;
            npr.w = sd.w * pr.w + pi.w * total.w;

            float vsc = (newv - vth) * invden;
            float z = (vsc > 0.0f) ? 1.0f : 0.0f;
            if (newr > 0.0f) z = 0.0f;
            nm |= (z != 0.0f ? 1u : 0u) << b;

            g_v[bn]  = newv;
            g_r[bn]  = newr;
            g_a1[bn] = na1;
            g_a2[bn] = na2;
            g_psc_rise[bn] = npr;
            g_psc[bn]      = npc;
            totcur[bn] = bk;                 // re-init for step t+2

            __stcs(&out[(t * BB + b) * NN + n], z);
        }
        g_zmask[h_write * NN + n] = (unsigned char)nm;

        if (nm) {
            g_any[5 + t] = 1;                // benign race (all write 1)
            if (t + 1 < TT) {
                float* totn = reinterpret_cast<float*>(totnxt);
                int base = n * D0_SLOT;
                int r1 = g_fill0[n];
                for (int e = base; e < r1; e++) {
                    int2 tw = g_d0_edge[e];
                    float w = __int_as_float(tw.y);
                    #pragma unroll
                    for (int b = 0; b < BB; b++) {
                        if (nm & (1u << b)) atomicAdd(&totn[b * RNN + tw.x], w);
                    }
                }
            }
        }
    } else {
        // --------------------- scatter role (step t+1) -----------------------
        if (t + 1 >= TT) return;
        const int tau = t + 1;
        float* totn = reinterpret_cast<float*>(totnxt);

        const int q1 = g_qoff[1];
        const int q2 = g_qoff[2];
        const int q3 = g_qoff[3];
        const int q4 = g_qoff[4];
        const int totq = q4 + IN_QUADS;

        int idx    = (blockIdx.x - U_BLKS) * blockDim.x + threadIdx.x;
        int stride = (gridDim.x - U_BLKS) * blockDim.x;

        for (int q = idx; q < totq; q += stride) {
            if (q < q4) {
                int d = 1 + (q >= q1) + (q >= q2) + (q >= q3);
                if (g_any[5 + t - d] == 0) continue;   // source step had no spikes
                int qbase = (d == 1) ? 0 : (d == 2) ? q1 : (d == 3) ? q2 : q3;
                const int e0 = (d - 1) * SEG_CAP + ((q - qbase) << 2);

                int slot = h_write + d; if (slot >= DD) slot -= DD;
                const unsigned char* zm = &g_zmask[slot * NN];

                ushort4 nn = *reinterpret_cast<const ushort4*>(&g_e_n16[e0]);
                unsigned m0 = zm[nn.x], m1 = zm[nn.y], m2 = zm[nn.z], m3 = zm[nn.w];
                if ((m0 | m1 | m2 | m3) == 0u) continue;

                int4   tg = *reinterpret_cast<const int4*>  (&g_e_tgt[e0]);
                float4 ww = *reinterpret_cast<const float4*>(&g_e_w[e0]);
                unsigned ms[4]  = {m0, m1, m2, m3};
                int      tgs[4] = {tg.x, tg.y, tg.z, tg.w};
                float    wws[4] = {ww.x, ww.y, ww.z, ww.w};
                #pragma unroll
                for (int k = 0; k < 4; k++) {
                    unsigned m = ms[k];
                    if (!m) continue;
                    #pragma unroll
                    for (int b = 0; b < BB; b++) {
                        if (m & (1u << b)) atomicAdd(&totn[b * RNN + tgs[k]], wws[k]);
                    }
                }
            } else {
                const int e0 = (q - q4) * 4;
                int4 si = *reinterpret_cast<const int4*>(&in_src[e0]);
                const unsigned char* xm = &g_xmask[tau * N_INN];
                unsigned m0 = xm[si.x], m1 = xm[si.y], m2 = xm[si.z], m3 = xm[si.w];
                if ((m0 | m1 | m2 | m3) == 0u) continue;

                int4   tg = *reinterpret_cast<const int4*>  (&in_tgt[e0]);
                float4 ww = *reinterpret_cast<const float4*>(&w_in[e0]);
                unsigned ms[4]  = {m0, m1, m2, m3};
                int      tgs[4] = {tg.x, tg.y, tg.z, tg.w};
                float    wws[4] = {ww.x, ww.y, ww.z, ww.w};
                #pragma unroll
                for (int k = 0; k < 4; k++) {
                    unsigned m = ms[k];
                    if (!m) continue;
                    #pragma unroll
                    for (int b = 0; b < BB; b++) {
                        if (m & (1u << b)) atomicAdd(&totn[b * RNN + tgs[k]], wws[k]);
                    }
                }
            }
        }
    }
}

// --------------------------------- launcher ----------------------------------
extern "C" void kernel_launch(void* const* d_in, const int* in_sizes, int n_in,
                              void* d_out, int out_size)
{
    const float* x        = (const float*)d_in[0];
    const float* w_rec    = (const float*)d_in[1];
    const int*   rec_src  = (const int*)  d_in[2];
    const int*   rec_tgt  = (const int*)  d_in[3];
    const float* w_in     = (const float*)d_in[4];
    const int*   in_src   = (const int*)  d_in[5];
    const int*   in_tgt   = (const int*)  d_in[6];
    const float* bkg_w    = (const float*)d_in[7];
    const float* decay    = (const float*)d_in[8];
    const float* cf       = (const float*)d_in[9];
    const float* v_th     = (const float*)d_in[10];
    const float* e_l      = (const float*)d_in[11];
    const float* v_reset  = (const float*)d_in[12];
    const float* t_ref    = (const float*)d_in[13];
    const float2* asc_amps = (const float2*)d_in[14];
    const float2* param_k  = (const float2*)d_in[15];
    const float* param_g   = (const float*)d_in[16];
    const float4* syn_decay   = (const float4*)d_in[17];
    const float4* psc_initial = (const float4*)d_in[18];
    const float* v0        = (const float*)d_in[19];
    float* out = (float*)d_out;

    init_kernel<<<1024, 256>>>(x, bkg_w, param_k, v0);
    partition_kernel<<<(E_RECN + 255) / 256, 256>>>(rec_src, rec_tgt, w_rec);
    s0_kernel<<<(IN_QUADS + 255) / 256, 256>>>(in_src, in_tgt, w_in);

    int h = 0;
    for (int t = 0; t < TT; t++) {
        int h_read  = h;
        int h_write = (h + DD - 1) % DD;
        fused_kernel<<<F_GRID, 256>>>(decay, cf, v_th, e_l, v_reset, t_ref,
                                      asc_amps, param_g, syn_decay, psc_initial,
                                      (const float4*)bkg_w,
                                      in_src, in_tgt, w_in,
                                      out, t, h_read, h_write);
        h = h_write;
    }
}